// round 11
// baseline (speedup 1.0000x reference)
#include <cuda_runtime.h>
#include <math.h>
#include <math_constants.h>

#define D_DIM 128
#define MAXN  50048
#define EPS_F 1e-8f
#define FULL  0xffffffffu
#define GAP_THRESH 0.01f

typedef unsigned int u32;

__device__ float g_xp[(size_t)MAXN * D_DIM];
__device__ int   g_flag[MAXN];
__device__ int   g_nflag;

// ---------------------------------------------------------------------------
// tf32 helpers
// ---------------------------------------------------------------------------
__device__ __forceinline__ u32 to_tf32(float x) {
    u32 r; asm("cvt.rna.tf32.f32 %0, %1;" : "=r"(r) : "f"(x)); return r;
}
__device__ __forceinline__ void split_tf32(float x, u32& hi, u32& lo) {
    hi = to_tf32(x);
    float rem = x - __uint_as_float(hi);
    lo = to_tf32(rem);
}
__device__ __forceinline__ void mma_tf32(float* c, const u32* a, const u32* b) {
    asm volatile(
        "mma.sync.aligned.m16n8k8.row.col.f32.tf32.tf32.f32 "
        "{%0,%1,%2,%3}, {%4,%5,%6,%7}, {%8,%9}, {%0,%1,%2,%3};"
        : "+f"(c[0]), "+f"(c[1]), "+f"(c[2]), "+f"(c[3])
        : "r"(a[0]), "r"(a[1]), "r"(a[2]), "r"(a[3]), "r"(b[0]), "r"(b[1]));
}

#define KC    32
#define PITCH 36
#define BUF_FLOATS (128 * PITCH)

// ---------------------------------------------------------------------------
// Projection: Y = (X @ W^T) * sqrt(softplus(logd)+eps), 4-pass split-TF32.
// ---------------------------------------------------------------------------
__global__ __launch_bounds__(512, 1) void proj_mma_kernel(
    const float* __restrict__ X, const float* __restrict__ W,
    const float* __restrict__ logd, int N)
{
    extern __shared__ float smem[];
    float* scale = smem;
    float* Xhi = smem + 128;
    float* Xlo = Xhi + BUF_FLOATS;
    float* Whi = Xlo + BUF_FLOATS;
    float* Wlo = Whi + BUF_FLOATS;

    const int tid  = threadIdx.x;
    const int lane = tid & 31;
    const int wid  = tid >> 5;
    const int wm   = wid & 3;
    const int wn   = wid >> 2;
    const int m0   = blockIdx.x * 128;

    if (tid < 128) {
        float ld = logd[tid];
        float sp = (ld > 20.f) ? ld : log1pf(expf(ld));
        scale[tid] = sqrtf(sp + EPS_F);
    }

    float acc[2][4][4];
#pragma unroll
    for (int mt = 0; mt < 2; mt++)
#pragma unroll
        for (int nt = 0; nt < 4; nt++)
#pragma unroll
            for (int q = 0; q < 4; q++) acc[mt][nt][q] = 0.f;

    const int fr = lane >> 2;
    const int fc = lane & 3;

    for (int kt = 0; kt < 4; kt++) {
        __syncthreads();
#pragma unroll
        for (int it = 0; it < 2; it++) {
            int idx = tid + it * 512;
            int r   = idx >> 3;
            int k4  = (idx & 7) * 4;
            int gr = m0 + r;
            float4 xv = make_float4(0.f, 0.f, 0.f, 0.f);
            if (gr < N) xv = *(const float4*)(X + (size_t)gr * D_DIM + kt * KC + k4);
            u32 h0, l0, h1, l1, h2, l2, h3, l3;
            split_tf32(xv.x, h0, l0); split_tf32(xv.y, h1, l1);
            split_tf32(xv.z, h2, l2); split_tf32(xv.w, h3, l3);
            u32* xh = (u32*)(Xhi + r * PITCH + k4);
            u32* xl = (u32*)(Xlo + r * PITCH + k4);
            xh[0] = h0; xh[1] = h1; xh[2] = h2; xh[3] = h3;
            xl[0] = l0; xl[1] = l1; xl[2] = l2; xl[3] = l3;
            float4 wv = *(const float4*)(W + (size_t)r * D_DIM + kt * KC + k4);
            split_tf32(wv.x, h0, l0); split_tf32(wv.y, h1, l1);
            split_tf32(wv.z, h2, l2); split_tf32(wv.w, h3, l3);
            u32* wh = (u32*)(Whi + r * PITCH + k4);
            u32* wl = (u32*)(Wlo + r * PITCH + k4);
            wh[0] = h0; wh[1] = h1; wh[2] = h2; wh[3] = h3;
            wl[0] = l0; wl[1] = l1; wl[2] = l2; wl[3] = l3;
        }
        __syncthreads();

#pragma unroll
        for (int ks = 0; ks < KC / 8; ks++) {
            u32 ah[2][4], al[2][4];
#pragma unroll
            for (int mt = 0; mt < 2; mt++) {
                int rb = (wm * 32 + mt * 16 + fr) * PITCH + ks * 8 + fc;
                ah[mt][0] = *(u32*)(Xhi + rb);
                ah[mt][1] = *(u32*)(Xhi + rb + 8 * PITCH);
                ah[mt][2] = *(u32*)(Xhi + rb + 4);
                ah[mt][3] = *(u32*)(Xhi + rb + 8 * PITCH + 4);
                al[mt][0] = *(u32*)(Xlo + rb);
                al[mt][1] = *(u32*)(Xlo + rb + 8 * PITCH);
                al[mt][2] = *(u32*)(Xlo + rb + 4);
                al[mt][3] = *(u32*)(Xlo + rb + 8 * PITCH + 4);
            }
            u32 bh[4][2], bl[4][2];
#pragma unroll
            for (int nt = 0; nt < 4; nt++) {
                int nb = (wn * 32 + nt * 8 + fr) * PITCH + ks * 8 + fc;
                bh[nt][0] = *(u32*)(Whi + nb);
                bh[nt][1] = *(u32*)(Whi + nb + 4);
                bl[nt][0] = *(u32*)(Wlo + nb);
                bl[nt][1] = *(u32*)(Wlo + nb + 4);
            }
#pragma unroll
            for (int mt = 0; mt < 2; mt++)
#pragma unroll
                for (int nt = 0; nt < 4; nt++) {
                    mma_tf32(acc[mt][nt], ah[mt], bh[nt]);
                    mma_tf32(acc[mt][nt], ah[mt], bl[nt]);
                    mma_tf32(acc[mt][nt], al[mt], bh[nt]);
                    mma_tf32(acc[mt][nt], al[mt], bl[nt]);
                }
        }
    }

#pragma unroll
    for (int mt = 0; mt < 2; mt++) {
        int row0 = m0 + wm * 32 + mt * 16 + fr;
#pragma unroll
        for (int nt = 0; nt < 4; nt++) {
            int col = wn * 32 + nt * 8 + 2 * fc;
            float s0 = scale[col], s1 = scale[col + 1];
            if (row0 < N) {
                float2 o0 = make_float2(acc[mt][nt][0] * s0, acc[mt][nt][1] * s1);
                *(float2*)(g_xp + (size_t)row0 * D_DIM + col) = o0;
            }
            if (row0 + 8 < N) {
                float2 o1 = make_float2(acc[mt][nt][2] * s0, acc[mt][nt][3] * s1);
                *(float2*)(g_xp + (size_t)(row0 + 8) * D_DIM + col) = o1;
            }
        }
    }
}

// ---------------------------------------------------------------------------
// Shared warp-level machinery (identical realization in edge + repair)
// ---------------------------------------------------------------------------
__device__ __forceinline__ float butterfly_score(float* p, int lane) {
    const bool b0 = lane & 1;
#pragma unroll
    for (int k = 0; k < 8; k++) {
        float send = b0 ? p[k] : p[k + 8];
        float recv = __shfl_xor_sync(FULL, send, 1);
        p[k] = (b0 ? p[k + 8] : p[k]) + recv;
    }
    const bool b1 = lane & 2;
#pragma unroll
    for (int k = 0; k < 4; k++) {
        float send = b1 ? p[k] : p[k + 4];
        float recv = __shfl_xor_sync(FULL, send, 2);
        p[k] = (b1 ? p[k + 4] : p[k]) + recv;
    }
    const bool b2 = lane & 4;
#pragma unroll
    for (int k = 0; k < 2; k++) {
        float send = b2 ? p[k] : p[k + 2];
        float recv = __shfl_xor_sync(FULL, send, 4);
        p[k] = (b2 ? p[k + 2] : p[k]) + recv;
    }
    const bool b3 = lane & 8;
    {
        float send = b3 ? p[0] : p[1];
        float recv = __shfl_xor_sync(FULL, send, 8);
        p[0] = (b3 ? p[1] : p[0]) + recv;
    }
    p[0] += __shfl_xor_sync(FULL, p[0], 16);
    const int l4  = lane & 15;
    const int rev = ((l4 & 1) << 3) | ((l4 & 2) << 1) | ((l4 & 4) >> 1) | ((l4 & 8) >> 3);
    return __shfl_sync(FULL, p[0], rev);
}

__device__ __forceinline__ void diff_sq(const float4& yi, const float4& v, float& outv) {
    float dx = yi.x - v.x, dy = yi.y - v.y;
    float dz = yi.z - v.z, dw = yi.w - v.w;
    outv = dx * dx + dy * dy + dz * dz + dw * dw;
}

__device__ __forceinline__ void finish_and_write(
    float s, bool sel, int lane, int i, int mycol,
    float* __restrict__ out, int N, int topk)
{
    unsigned bal = __ballot_sync(FULL, sel);
    float smax = sel ? s : -CUDART_INF_F;
#pragma unroll
    for (int o = 8; o > 0; o >>= 1)
        smax = fmaxf(smax, __shfl_xor_sync(FULL, smax, o));
    float e = sel ? expf(s - smax) : 0.f;
    float esum = e;
#pragma unroll
    for (int o = 8; o > 0; o >>= 1)
        esum += __shfl_xor_sync(FULL, esum, o);
    if (sel) {
        float w = e / esum;
        int k = __popc(bal & ((1u << lane) - 1u));
        size_t NT = (size_t)N * topk;
        size_t base = (size_t)i * topk + k;
        out[base]          = (float)i;
        out[NT + base]     = (float)mycol;
        out[2 * NT + base] = w;
    }
}

// ---------------------------------------------------------------------------
// Reset kernel: clear the flagged-node counter (deterministic each replay).
// ---------------------------------------------------------------------------
__global__ void reset_kernel() { g_nflag = 0; }

// ---------------------------------------------------------------------------
// Edge kernel (R7 fast shape): MMA-y scores; small-margin nodes are flagged
// for exact repair and produce no output here.
// ---------------------------------------------------------------------------
__global__ __launch_bounds__(256, 5) void edge_kernel(
    const int* __restrict__ eidx, const float* __restrict__ logt,
    float* __restrict__ out, int N, int deg, int topk)
{
    const int warp = blockIdx.x * (blockDim.x >> 5) + (threadIdx.x >> 5);
    const int lane = threadIdx.x & 31;
    if (warp >= N) return;
    const int i = warp;

    const int* colp = eidx + (size_t)N * deg + (size_t)i * deg;
    int mycol = (lane < 16) ? colp[lane] : 0;

    const float rtemp = expf(-logt[0]);

    float4 yi = *(const float4*)(g_xp + (size_t)i * D_DIM + lane * 4);
    float p[16];
#pragma unroll
    for (int g = 0; g < 4; g++) {
        float4 v[4];
#pragma unroll
        for (int n = 0; n < 4; n++) {
            int c = __shfl_sync(FULL, mycol, g * 4 + n);
            v[n] = *(const float4*)(g_xp + (size_t)c * D_DIM + lane * 4);
        }
#pragma unroll
        for (int n = 0; n < 4; n++) diff_sq(yi, v[n], p[g * 4 + n]);
    }
    float raw = butterfly_score(p, lane);
    float s = (lane < 16) ? (-raw * rtemp) : -CUDART_INF_F;

    int rank = 0;
#pragma unroll
    for (int m = 0; m < 16; m++) {
        float sm = __shfl_sync(FULL, s, m);
        rank += (sm > s || (sm == s && m < lane)) ? 1 : 0;
    }
    bool sel = rank < topk;

    // selection margin: min(selected) - max(unselected)
    float m1 = sel ? s : CUDART_INF_F;
    float m2 = (!sel && lane < 16) ? s : -CUDART_INF_F;
#pragma unroll
    for (int o = 16; o > 0; o >>= 1) {
        m1 = fminf(m1, __shfl_xor_sync(FULL, m1, o));
        m2 = fmaxf(m2, __shfl_xor_sync(FULL, m2, o));
    }
    if (m1 - m2 < GAP_THRESH) {
        if (lane == 0) {
            int idx = atomicAdd(&g_nflag, 1);
            g_flag[idx] = i;
        }
        return;   // repair kernel owns this node's output
    }

    finish_and_write(s, sel, lane, i, mycol, out, N, topk);
}

// ---------------------------------------------------------------------------
// Repair kernel: one block per flagged node. Recomputes the 17 needed y-rows
// exactly (fmaf ascending k, then *sqrt(softplus+eps) — bitwise identical to
// the fp32-sequential realization), then reruns identical score machinery.
// ---------------------------------------------------------------------------
#define NCHAIN (17 * 128)

__global__ __launch_bounds__(256) void repair_kernel(
    const int* __restrict__ eidx, const float* __restrict__ logt,
    const float* __restrict__ X, const float* __restrict__ W,
    const float* __restrict__ logd,
    float* __restrict__ out, int N, int deg, int topk)
{
    __shared__ __align__(16) float ys[NCHAIN];   // rows 0..15 = neighbors, 16 = self
    __shared__ int cols_s[16];
    const int tid = threadIdx.x;
    const int nf = g_nflag;

    for (int f = blockIdx.x; f < nf; f += gridDim.x) {
        const int i = g_flag[f];
        if (tid < 16) cols_s[tid] = eidx[(size_t)N * deg + (size_t)i * deg + tid];
        __syncthreads();

        for (int base = tid; base < NCHAIN; base += 512) {
            int idx0 = base;
            int idx1 = base + 256;
            bool has1 = idx1 < NCHAIN;
            int r0 = idx0 >> 7, c0 = idx0 & 127;
            int row0 = (r0 == 16) ? i : cols_s[r0];
            int r1 = has1 ? (idx1 >> 7) : r0;
            int c1 = has1 ? (idx1 & 127) : c0;
            int row1 = (r1 == 16) ? i : cols_s[r1];
            const float* xr0 = X + (size_t)row0 * D_DIM;
            const float* wc0 = W + (size_t)c0 * D_DIM;
            const float* xr1 = X + (size_t)row1 * D_DIM;
            const float* wc1 = W + (size_t)c1 * D_DIM;
            float a0 = 0.f, a1 = 0.f;
#pragma unroll 8
            for (int k = 0; k < D_DIM; k++) {
                a0 = fmaf(xr0[k], wc0[k], a0);
                a1 = fmaf(xr1[k], wc1[k], a1);
            }
            {
                float ldv = logd[c0];
                float sp = (ldv > 20.f) ? ldv : log1pf(expf(ldv));
                ys[idx0] = a0 * sqrtf(sp + EPS_F);
            }
            if (has1) {
                float ldv = logd[c1];
                float sp = (ldv > 20.f) ? ldv : log1pf(expf(ldv));
                ys[idx1] = a1 * sqrtf(sp + EPS_F);
            }
        }
        __syncthreads();

        if (tid < 32) {
            const int lane = tid;
            int mycol = (lane < 16) ? cols_s[lane] : 0;
            const float rtemp = expf(-logt[0]);
            float4 yi = *(const float4*)(ys + 16 * 128 + lane * 4);
            float p[16];
#pragma unroll
            for (int n = 0; n < 16; n++) {
                float4 v = *(const float4*)(ys + n * 128 + lane * 4);
                diff_sq(yi, v, p[n]);
            }
            float rawv = butterfly_score(p, lane);
            float s = (lane < 16) ? (-rawv * rtemp) : -CUDART_INF_F;
            int rank = 0;
#pragma unroll
            for (int m = 0; m < 16; m++) {
                float sm = __shfl_sync(FULL, s, m);
                rank += (sm > s || (sm == s && m < lane)) ? 1 : 0;
            }
            bool sel = rank < topk;
            finish_and_write(s, sel, lane, i, mycol, out, N, topk);
        }
        __syncthreads();
    }
}

// ---------------------------------------------------------------------------
extern "C" void kernel_launch(void* const* d_in, const int* in_sizes, int n_in,
                              void* d_out, int out_size)
{
    const float* x    = (const float*)d_in[0];
    const int*   eidx = (const int*)  d_in[1];
    const float* W    = (const float*)d_in[2];
    const float* logd = (const float*)d_in[3];
    const float* logt = (const float*)d_in[4];

    const int D   = 128;
    const int N   = in_sizes[0] / D;
    const int deg = in_sizes[1] / (2 * N);
    const int topk = out_size / (3 * N);

    float* out = (float*)d_out;

    reset_kernel<<<1, 1>>>();

    const int smem_bytes = (128 + 4 * BUF_FLOATS) * sizeof(float);
    cudaFuncSetAttribute(proj_mma_kernel,
                         cudaFuncAttributeMaxDynamicSharedMemorySize, smem_bytes);
    proj_mma_kernel<<<(N + 127) / 128, 512, smem_bytes>>>(x, W, logd, N);

    int warps_per_block = 256 / 32;
    int blocks = (N + warps_per_block - 1) / warps_per_block;
    edge_kernel<<<blocks, 256>>>(eidx, logt, out, N, deg, topk);

    repair_kernel<<<64, 256>>>(eidx, logt, x, W, logd, out, N, deg, topk);
}

// round 13
// speedup vs baseline: 3.7712x; 3.7712x over previous
#include <cuda_runtime.h>
#include <math.h>
#include <math_constants.h>

#define D_DIM 128
#define MAXN  50048
#define EPS_F 1e-8f
#define FULL  0xffffffffu
#define GAP_THRESH 0.01f

typedef unsigned int u32;

__device__ float g_xp[(size_t)MAXN * D_DIM];
__device__ int   g_flag[MAXN];
__device__ int   g_nflag;

// ---------------------------------------------------------------------------
// tf32 helpers
// ---------------------------------------------------------------------------
__device__ __forceinline__ u32 to_tf32(float x) {
    u32 r; asm("cvt.rna.tf32.f32 %0, %1;" : "=r"(r) : "f"(x)); return r;
}
__device__ __forceinline__ void split_tf32(float x, u32& hi, u32& lo) {
    hi = to_tf32(x);
    float rem = x - __uint_as_float(hi);
    lo = to_tf32(rem);
}
__device__ __forceinline__ void mma_tf32(float* c, const u32* a, const u32* b) {
    asm volatile(
        "mma.sync.aligned.m16n8k8.row.col.f32.tf32.tf32.f32 "
        "{%0,%1,%2,%3}, {%4,%5,%6,%7}, {%8,%9}, {%0,%1,%2,%3};"
        : "+f"(c[0]), "+f"(c[1]), "+f"(c[2]), "+f"(c[3])
        : "r"(a[0]), "r"(a[1]), "r"(a[2]), "r"(a[3]), "r"(b[0]), "r"(b[1]));
}

#define KC    32
#define PITCH 36
#define BUF_FLOATS (128 * PITCH)

// ---------------------------------------------------------------------------
// Projection: Y = (X @ W^T) * sqrt(softplus(logd)+eps), 3-pass split-TF32
// (hi*hi + hi*lo + lo*hi). Residual ~7e-6 score noise is caught by the
// margin check + repair kernel.
// ---------------------------------------------------------------------------
__global__ __launch_bounds__(512, 1) void proj_mma_kernel(
    const float* __restrict__ X, const float* __restrict__ W,
    const float* __restrict__ logd, int N)
{
    extern __shared__ float smem[];
    float* scale = smem;
    float* Xhi = smem + 128;
    float* Xlo = Xhi + BUF_FLOATS;
    float* Whi = Xlo + BUF_FLOATS;
    float* Wlo = Whi + BUF_FLOATS;

    const int tid  = threadIdx.x;
    const int lane = tid & 31;
    const int wid  = tid >> 5;
    const int wm   = wid & 3;
    const int wn   = wid >> 2;
    const int m0   = blockIdx.x * 128;

    if (tid < 128) {
        float ld = logd[tid];
        float sp = (ld > 20.f) ? ld : log1pf(expf(ld));
        scale[tid] = sqrtf(sp + EPS_F);
    }

    float acc[2][4][4];
#pragma unroll
    for (int mt = 0; mt < 2; mt++)
#pragma unroll
        for (int nt = 0; nt < 4; nt++)
#pragma unroll
            for (int q = 0; q < 4; q++) acc[mt][nt][q] = 0.f;

    const int fr = lane >> 2;
    const int fc = lane & 3;

    for (int kt = 0; kt < 4; kt++) {
        __syncthreads();
#pragma unroll
        for (int it = 0; it < 2; it++) {
            int idx = tid + it * 512;
            int r   = idx >> 3;
            int k4  = (idx & 7) * 4;
            int gr = m0 + r;
            float4 xv = make_float4(0.f, 0.f, 0.f, 0.f);
            if (gr < N) xv = *(const float4*)(X + (size_t)gr * D_DIM + kt * KC + k4);
            u32 h0, l0, h1, l1, h2, l2, h3, l3;
            split_tf32(xv.x, h0, l0); split_tf32(xv.y, h1, l1);
            split_tf32(xv.z, h2, l2); split_tf32(xv.w, h3, l3);
            u32* xh = (u32*)(Xhi + r * PITCH + k4);
            u32* xl = (u32*)(Xlo + r * PITCH + k4);
            xh[0] = h0; xh[1] = h1; xh[2] = h2; xh[3] = h3;
            xl[0] = l0; xl[1] = l1; xl[2] = l2; xl[3] = l3;
            float4 wv = *(const float4*)(W + (size_t)r * D_DIM + kt * KC + k4);
            split_tf32(wv.x, h0, l0); split_tf32(wv.y, h1, l1);
            split_tf32(wv.z, h2, l2); split_tf32(wv.w, h3, l3);
            u32* wh = (u32*)(Whi + r * PITCH + k4);
            u32* wl = (u32*)(Wlo + r * PITCH + k4);
            wh[0] = h0; wh[1] = h1; wh[2] = h2; wh[3] = h3;
            wl[0] = l0; wl[1] = l1; wl[2] = l2; wl[3] = l3;
        }
        __syncthreads();

#pragma unroll
        for (int ks = 0; ks < KC / 8; ks++) {
            u32 ah[2][4], al[2][4];
#pragma unroll
            for (int mt = 0; mt < 2; mt++) {
                int rb = (wm * 32 + mt * 16 + fr) * PITCH + ks * 8 + fc;
                ah[mt][0] = *(u32*)(Xhi + rb);
                ah[mt][1] = *(u32*)(Xhi + rb + 8 * PITCH);
                ah[mt][2] = *(u32*)(Xhi + rb + 4);
                ah[mt][3] = *(u32*)(Xhi + rb + 8 * PITCH + 4);
                al[mt][0] = *(u32*)(Xlo + rb);
                al[mt][1] = *(u32*)(Xlo + rb + 8 * PITCH);
                al[mt][2] = *(u32*)(Xlo + rb + 4);
                al[mt][3] = *(u32*)(Xlo + rb + 8 * PITCH + 4);
            }
            u32 bh[4][2], bl[4][2];
#pragma unroll
            for (int nt = 0; nt < 4; nt++) {
                int nb = (wn * 32 + nt * 8 + fr) * PITCH + ks * 8 + fc;
                bh[nt][0] = *(u32*)(Whi + nb);
                bh[nt][1] = *(u32*)(Whi + nb + 4);
                bl[nt][0] = *(u32*)(Wlo + nb);
                bl[nt][1] = *(u32*)(Wlo + nb + 4);
            }
#pragma unroll
            for (int mt = 0; mt < 2; mt++)
#pragma unroll
                for (int nt = 0; nt < 4; nt++) {
                    mma_tf32(acc[mt][nt], ah[mt], bh[nt]);
                    mma_tf32(acc[mt][nt], ah[mt], bl[nt]);
                    mma_tf32(acc[mt][nt], al[mt], bh[nt]);
                }
        }
    }

#pragma unroll
    for (int mt = 0; mt < 2; mt++) {
        int row0 = m0 + wm * 32 + mt * 16 + fr;
#pragma unroll
        for (int nt = 0; nt < 4; nt++) {
            int col = wn * 32 + nt * 8 + 2 * fc;
            float s0 = scale[col], s1 = scale[col + 1];
            if (row0 < N) {
                float2 o0 = make_float2(acc[mt][nt][0] * s0, acc[mt][nt][1] * s1);
                *(float2*)(g_xp + (size_t)row0 * D_DIM + col) = o0;
            }
            if (row0 + 8 < N) {
                float2 o1 = make_float2(acc[mt][nt][2] * s0, acc[mt][nt][3] * s1);
                *(float2*)(g_xp + (size_t)(row0 + 8) * D_DIM + col) = o1;
            }
        }
    }
}

// ---------------------------------------------------------------------------
// Shared warp-level machinery (identical realization in edge + repair)
// ---------------------------------------------------------------------------
__device__ __forceinline__ float butterfly_score(float* p, int lane) {
    const bool b0 = lane & 1;
#pragma unroll
    for (int k = 0; k < 8; k++) {
        float send = b0 ? p[k] : p[k + 8];
        float recv = __shfl_xor_sync(FULL, send, 1);
        p[k] = (b0 ? p[k + 8] : p[k]) + recv;
    }
    const bool b1 = lane & 2;
#pragma unroll
    for (int k = 0; k < 4; k++) {
        float send = b1 ? p[k] : p[k + 4];
        float recv = __shfl_xor_sync(FULL, send, 2);
        p[k] = (b1 ? p[k + 4] : p[k]) + recv;
    }
    const bool b2 = lane & 4;
#pragma unroll
    for (int k = 0; k < 2; k++) {
        float send = b2 ? p[k] : p[k + 2];
        float recv = __shfl_xor_sync(FULL, send, 4);
        p[k] = (b2 ? p[k + 2] : p[k]) + recv;
    }
    const bool b3 = lane & 8;
    {
        float send = b3 ? p[0] : p[1];
        float recv = __shfl_xor_sync(FULL, send, 8);
        p[0] = (b3 ? p[1] : p[0]) + recv;
    }
    p[0] += __shfl_xor_sync(FULL, p[0], 16);
    const int l4  = lane & 15;
    const int rev = ((l4 & 1) << 3) | ((l4 & 2) << 1) | ((l4 & 4) >> 1) | ((l4 & 8) >> 3);
    return __shfl_sync(FULL, p[0], rev);
}

__device__ __forceinline__ void diff_sq(const float4& yi, const float4& v, float& outv) {
    float dx = yi.x - v.x, dy = yi.y - v.y;
    float dz = yi.z - v.z, dw = yi.w - v.w;
    outv = dx * dx + dy * dy + dz * dz + dw * dw;
}

__device__ __forceinline__ void finish_and_write(
    float s, bool sel, int lane, int i, int mycol,
    float* __restrict__ out, int N, int topk)
{
    unsigned bal = __ballot_sync(FULL, sel);
    float smax = sel ? s : -CUDART_INF_F;
#pragma unroll
    for (int o = 8; o > 0; o >>= 1)
        smax = fmaxf(smax, __shfl_xor_sync(FULL, smax, o));
    float e = sel ? expf(s - smax) : 0.f;
    float esum = e;
#pragma unroll
    for (int o = 8; o > 0; o >>= 1)
        esum += __shfl_xor_sync(FULL, esum, o);
    if (sel) {
        float w = e / esum;
        int k = __popc(bal & ((1u << lane) - 1u));
        size_t NT = (size_t)N * topk;
        size_t base = (size_t)i * topk + k;
        out[base]          = (float)i;
        out[NT + base]     = (float)mycol;
        out[2 * NT + base] = w;
    }
}

// ---------------------------------------------------------------------------
__global__ void reset_kernel() { g_nflag = 0; }

// ---------------------------------------------------------------------------
// Edge kernel (fast shape): MMA-y scores; small-margin nodes are flagged
// for exact repair and produce no output here.
// ---------------------------------------------------------------------------
__global__ __launch_bounds__(256, 5) void edge_kernel(
    const int* __restrict__ eidx, const float* __restrict__ logt,
    float* __restrict__ out, int N, int deg, int topk)
{
    const int warp = blockIdx.x * (blockDim.x >> 5) + (threadIdx.x >> 5);
    const int lane = threadIdx.x & 31;
    if (warp >= N) return;
    const int i = warp;

    const int* colp = eidx + (size_t)N * deg + (size_t)i * deg;
    int mycol = (lane < 16) ? colp[lane] : 0;

    const float rtemp = expf(-logt[0]);

    float4 yi = *(const float4*)(g_xp + (size_t)i * D_DIM + lane * 4);
    float p[16];
#pragma unroll
    for (int g = 0; g < 4; g++) {
        float4 v[4];
#pragma unroll
        for (int n = 0; n < 4; n++) {
            int c = __shfl_sync(FULL, mycol, g * 4 + n);
            v[n] = *(const float4*)(g_xp + (size_t)c * D_DIM + lane * 4);
        }
#pragma unroll
        for (int n = 0; n < 4; n++) diff_sq(yi, v[n], p[g * 4 + n]);
    }
    float raw = butterfly_score(p, lane);
    float s = (lane < 16) ? (-raw * rtemp) : -CUDART_INF_F;

    int rank = 0;
#pragma unroll
    for (int m = 0; m < 16; m++) {
        float sm = __shfl_sync(FULL, s, m);
        rank += (sm > s || (sm == s && m < lane)) ? 1 : 0;
    }
    bool sel = rank < topk;

    float m1 = sel ? s : CUDART_INF_F;
    float m2 = (!sel && lane < 16) ? s : -CUDART_INF_F;
#pragma unroll
    for (int o = 16; o > 0; o >>= 1) {
        m1 = fminf(m1, __shfl_xor_sync(FULL, m1, o));
        m2 = fmaxf(m2, __shfl_xor_sync(FULL, m2, o));
    }
    if (m1 - m2 < GAP_THRESH) {
        if (lane == 0) {
            int idx = atomicAdd(&g_nflag, 1);
            g_flag[idx] = i;
        }
        return;   // repair kernel owns this node's output
    }

    finish_and_write(s, sel, lane, i, mycol, out, N, topk);
}

// ---------------------------------------------------------------------------
// Repair kernel v2: one block per flagged node, smem-staged and conflict-free.
// W staged once per block at pitch 129 (bank = (c+k)%32 over consecutive-c
// lanes: conflict-free). Each thread runs two interleaved ascending-k fmaf
// chains sharing one W load per k — bitwise-identical realization to the
// fp32-sequential projection.
// ---------------------------------------------------------------------------
#define RW_PITCH 129
// smem floats: Ws 128*129 =16512, Xs 17*128=2176, ys 17*128=2176, scale 128
#define REPAIR_SMEM_FLOATS (128 * RW_PITCH + 2176 + 2176 + 128)

__global__ __launch_bounds__(256) void repair_kernel(
    const int* __restrict__ eidx, const float* __restrict__ logt,
    const float* __restrict__ X, const float* __restrict__ W,
    const float* __restrict__ logd,
    float* __restrict__ out, int N, int deg, int topk)
{
    extern __shared__ float rsm[];
    float* Ws = rsm;
    float* Xs = rsm + 128 * RW_PITCH;
    float* ys = Xs + 17 * 128;
    float* sc = ys + 17 * 128;
    __shared__ int cols_s[17];

    const int tid = threadIdx.x;

    // stage W (once per block): coalesced float4 reads
    for (int t = tid; t < 128 * 32; t += 256) {
        int c  = t >> 5;
        int kq = (t & 31) * 4;
        float4 wv = *(const float4*)(W + (size_t)c * D_DIM + kq);
        Ws[c * RW_PITCH + kq + 0] = wv.x;
        Ws[c * RW_PITCH + kq + 1] = wv.y;
        Ws[c * RW_PITCH + kq + 2] = wv.z;
        Ws[c * RW_PITCH + kq + 3] = wv.w;
    }
    if (tid < 128) {
        float ld = logd[tid];
        float sp = (ld > 20.f) ? ld : log1pf(expf(ld));
        sc[tid] = sqrtf(sp + EPS_F);
    }

    const int nf = g_nflag;

    for (int f = blockIdx.x; f < nf; f += gridDim.x) {
        __syncthreads();
        const int i = g_flag[f];
        if (tid < 16) cols_s[tid] = eidx[(size_t)N * deg + (size_t)i * deg + tid];
        if (tid == 16) cols_s[16] = i;
        __syncthreads();

        // stage the 17 needed X rows: 17 rows x 32 float4
        for (int t = tid; t < 17 * 32; t += 256) {
            int r  = t >> 5;
            int kq = (t & 31) * 4;
            int row = cols_s[r];
            float4 xv = *(const float4*)(X + (size_t)row * D_DIM + kq);
            *(float4*)(Xs + r * 128 + kq) = xv;
        }
        __syncthreads();

        // 2176 chains: c = tid&127, two interleaved ascending-k fmaf chains
        const int c  = tid & 127;
        const int rp = tid >> 7;
        const float* wr = Ws + c * RW_PITCH;
        const float scv = sc[c];
#pragma unroll
        for (int gg = 0; gg < 5; gg++) {
            int rA = rp + 4 * gg;
            int rB = rp + 4 * gg + 2;
            bool hA = rA < 17, hB = rB < 17;
            const float* xA = Xs + (hA ? rA : 0) * 128;
            const float* xB = Xs + (hB ? rB : 0) * 128;
            float a = 0.f, b = 0.f;
#pragma unroll 16
            for (int k = 0; k < D_DIM; k++) {
                float wv = wr[k];
                a = fmaf(xA[k], wv, a);
                b = fmaf(xB[k], wv, b);
            }
            if (hA) ys[rA * 128 + c] = a * scv;
            if (hB) ys[rB * 128 + c] = b * scv;
        }
        __syncthreads();

        if (tid < 32) {
            const int lane = tid;
            int mycol = (lane < 16) ? cols_s[lane] : 0;
            const float rtemp = expf(-logt[0]);
            float4 yi = *(const float4*)(ys + 16 * 128 + lane * 4);
            float p[16];
#pragma unroll
            for (int n = 0; n < 16; n++) {
                float4 v = *(const float4*)(ys + n * 128 + lane * 4);
                diff_sq(yi, v, p[n]);
            }
            float rawv = butterfly_score(p, lane);
            float s = (lane < 16) ? (-rawv * rtemp) : -CUDART_INF_F;
            int rank = 0;
#pragma unroll
            for (int m = 0; m < 16; m++) {
                float sm = __shfl_sync(FULL, s, m);
                rank += (sm > s || (sm == s && m < lane)) ? 1 : 0;
            }
            bool sel = rank < topk;
            finish_and_write(s, sel, lane, i, mycol, out, N, topk);
        }
    }
}

// ---------------------------------------------------------------------------
extern "C" void kernel_launch(void* const* d_in, const int* in_sizes, int n_in,
                              void* d_out, int out_size)
{
    const float* x    = (const float*)d_in[0];
    const int*   eidx = (const int*)  d_in[1];
    const float* W    = (const float*)d_in[2];
    const float* logd = (const float*)d_in[3];
    const float* logt = (const float*)d_in[4];

    const int D   = 128;
    const int N   = in_sizes[0] / D;
    const int deg = in_sizes[1] / (2 * N);
    const int topk = out_size / (3 * N);

    float* out = (float*)d_out;

    reset_kernel<<<1, 1>>>();

    const int smem_bytes = (128 + 4 * BUF_FLOATS) * sizeof(float);
    cudaFuncSetAttribute(proj_mma_kernel,
                         cudaFuncAttributeMaxDynamicSharedMemorySize, smem_bytes);
    proj_mma_kernel<<<(N + 127) / 128, 512, smem_bytes>>>(x, W, logd, N);

    int warps_per_block = 256 / 32;
    int blocks = (N + warps_per_block - 1) / warps_per_block;
    edge_kernel<<<blocks, 256>>>(eidx, logt, out, N, deg, topk);

    const int repair_smem = REPAIR_SMEM_FLOATS * sizeof(float);
    cudaFuncSetAttribute(repair_kernel,
                         cudaFuncAttributeMaxDynamicSharedMemorySize, repair_smem);
    repair_kernel<<<148, 256, repair_smem>>>(eidx, logt, x, W, logd, out, N, deg, topk);
}

// round 14
// speedup vs baseline: 3.7791x; 1.0021x over previous
#include <cuda_runtime.h>
#include <math.h>
#include <math_constants.h>

#define D_DIM 128
#define MAXN  50048
#define EPS_F 1e-8f
#define FULL  0xffffffffu
#define GAP_THRESH 1e-3f

typedef unsigned int u32;

__device__ float g_xp[(size_t)MAXN * D_DIM];
__device__ int   g_flag[MAXN];
__device__ int   g_nflag;

// ---------------------------------------------------------------------------
// tf32 helpers
// ---------------------------------------------------------------------------
__device__ __forceinline__ u32 to_tf32(float x) {
    u32 r; asm("cvt.rna.tf32.f32 %0, %1;" : "=r"(r) : "f"(x)); return r;
}
__device__ __forceinline__ void split_tf32(float x, u32& hi, u32& lo) {
    hi = to_tf32(x);
    float rem = x - __uint_as_float(hi);
    lo = to_tf32(rem);
}
__device__ __forceinline__ void mma_tf32(float* c, const u32* a, const u32* b) {
    asm volatile(
        "mma.sync.aligned.m16n8k8.row.col.f32.tf32.tf32.f32 "
        "{%0,%1,%2,%3}, {%4,%5,%6,%7}, {%8,%9}, {%0,%1,%2,%3};"
        : "+f"(c[0]), "+f"(c[1]), "+f"(c[2]), "+f"(c[3])
        : "r"(a[0]), "r"(a[1]), "r"(a[2]), "r"(a[3]), "r"(b[0]), "r"(b[1]));
}

#define KC    32
#define PITCH 36
#define BUF_FLOATS (128 * PITCH)

// ---------------------------------------------------------------------------
// Projection: Y = (X @ W^T) * sqrt(softplus(logd)+eps), 3-pass split-TF32
// (hi*hi + hi*lo + lo*hi). Residual ~2e-5 score noise is caught by the
// margin check + repair kernel. Also clears the flag counter (runs before
// edge in stream order).
// ---------------------------------------------------------------------------
__global__ __launch_bounds__(512, 1) void proj_mma_kernel(
    const float* __restrict__ X, const float* __restrict__ W,
    const float* __restrict__ logd, int N)
{
    extern __shared__ float smem[];
    float* scale = smem;
    float* Xhi = smem + 128;
    float* Xlo = Xhi + BUF_FLOATS;
    float* Whi = Xlo + BUF_FLOATS;
    float* Wlo = Whi + BUF_FLOATS;

    const int tid  = threadIdx.x;
    const int lane = tid & 31;
    const int wid  = tid >> 5;
    const int wm   = wid & 3;
    const int wn   = wid >> 2;
    const int m0   = blockIdx.x * 128;

    if (blockIdx.x == 0 && tid == 0) g_nflag = 0;

    if (tid < 128) {
        float ld = logd[tid];
        float sp = (ld > 20.f) ? ld : log1pf(expf(ld));
        scale[tid] = sqrtf(sp + EPS_F);
    }

    float acc[2][4][4];
#pragma unroll
    for (int mt = 0; mt < 2; mt++)
#pragma unroll
        for (int nt = 0; nt < 4; nt++)
#pragma unroll
            for (int q = 0; q < 4; q++) acc[mt][nt][q] = 0.f;

    const int fr = lane >> 2;
    const int fc = lane & 3;

    for (int kt = 0; kt < 4; kt++) {
        __syncthreads();
#pragma unroll
        for (int it = 0; it < 2; it++) {
            int idx = tid + it * 512;
            int r   = idx >> 3;
            int k4  = (idx & 7) * 4;
            int gr = m0 + r;
            float4 xv = make_float4(0.f, 0.f, 0.f, 0.f);
            if (gr < N) xv = *(const float4*)(X + (size_t)gr * D_DIM + kt * KC + k4);
            u32 h0, l0, h1, l1, h2, l2, h3, l3;
            split_tf32(xv.x, h0, l0); split_tf32(xv.y, h1, l1);
            split_tf32(xv.z, h2, l2); split_tf32(xv.w, h3, l3);
            u32* xh = (u32*)(Xhi + r * PITCH + k4);
            u32* xl = (u32*)(Xlo + r * PITCH + k4);
            xh[0] = h0; xh[1] = h1; xh[2] = h2; xh[3] = h3;
            xl[0] = l0; xl[1] = l1; xl[2] = l2; xl[3] = l3;
            float4 wv = *(const float4*)(W + (size_t)r * D_DIM + kt * KC + k4);
            split_tf32(wv.x, h0, l0); split_tf32(wv.y, h1, l1);
            split_tf32(wv.z, h2, l2); split_tf32(wv.w, h3, l3);
            u32* wh = (u32*)(Whi + r * PITCH + k4);
            u32* wl = (u32*)(Wlo + r * PITCH + k4);
            wh[0] = h0; wh[1] = h1; wh[2] = h2; wh[3] = h3;
            wl[0] = l0; wl[1] = l1; wl[2] = l2; wl[3] = l3;
        }
        __syncthreads();

#pragma unroll
        for (int ks = 0; ks < KC / 8; ks++) {
            u32 ah[2][4], al[2][4];
#pragma unroll
            for (int mt = 0; mt < 2; mt++) {
                int rb = (wm * 32 + mt * 16 + fr) * PITCH + ks * 8 + fc;
                ah[mt][0] = *(u32*)(Xhi + rb);
                ah[mt][1] = *(u32*)(Xhi + rb + 8 * PITCH);
                ah[mt][2] = *(u32*)(Xhi + rb + 4);
                ah[mt][3] = *(u32*)(Xhi + rb + 8 * PITCH + 4);
                al[mt][0] = *(u32*)(Xlo + rb);
                al[mt][1] = *(u32*)(Xlo + rb + 8 * PITCH);
                al[mt][2] = *(u32*)(Xlo + rb + 4);
                al[mt][3] = *(u32*)(Xlo + rb + 8 * PITCH + 4);
            }
            u32 bh[4][2], bl[4][2];
#pragma unroll
            for (int nt = 0; nt < 4; nt++) {
                int nb = (wn * 32 + nt * 8 + fr) * PITCH + ks * 8 + fc;
                bh[nt][0] = *(u32*)(Whi + nb);
                bh[nt][1] = *(u32*)(Whi + nb + 4);
                bl[nt][0] = *(u32*)(Wlo + nb);
                bl[nt][1] = *(u32*)(Wlo + nb + 4);
            }
#pragma unroll
            for (int mt = 0; mt < 2; mt++)
#pragma unroll
                for (int nt = 0; nt < 4; nt++) {
                    mma_tf32(acc[mt][nt], ah[mt], bh[nt]);
                    mma_tf32(acc[mt][nt], ah[mt], bl[nt]);
                    mma_tf32(acc[mt][nt], al[mt], bh[nt]);
                }
        }
    }

#pragma unroll
    for (int mt = 0; mt < 2; mt++) {
        int row0 = m0 + wm * 32 + mt * 16 + fr;
#pragma unroll
        for (int nt = 0; nt < 4; nt++) {
            int col = wn * 32 + nt * 8 + 2 * fc;
            float s0 = scale[col], s1 = scale[col + 1];
            if (row0 < N) {
                float2 o0 = make_float2(acc[mt][nt][0] * s0, acc[mt][nt][1] * s1);
                *(float2*)(g_xp + (size_t)row0 * D_DIM + col) = o0;
            }
            if (row0 + 8 < N) {
                float2 o1 = make_float2(acc[mt][nt][2] * s0, acc[mt][nt][3] * s1);
                *(float2*)(g_xp + (size_t)(row0 + 8) * D_DIM + col) = o1;
            }
        }
    }
}

// ---------------------------------------------------------------------------
// Shared warp-level machinery (identical realization in edge + repair)
// ---------------------------------------------------------------------------
__device__ __forceinline__ float butterfly_score(float* p, int lane) {
    const bool b0 = lane & 1;
#pragma unroll
    for (int k = 0; k < 8; k++) {
        float send = b0 ? p[k] : p[k + 8];
        float recv = __shfl_xor_sync(FULL, send, 1);
        p[k] = (b0 ? p[k + 8] : p[k]) + recv;
    }
    const bool b1 = lane & 2;
#pragma unroll
    for (int k = 0; k < 4; k++) {
        float send = b1 ? p[k] : p[k + 4];
        float recv = __shfl_xor_sync(FULL, send, 2);
        p[k] = (b1 ? p[k + 4] : p[k]) + recv;
    }
    const bool b2 = lane & 4;
#pragma unroll
    for (int k = 0; k < 2; k++) {
        float send = b2 ? p[k] : p[k + 2];
        float recv = __shfl_xor_sync(FULL, send, 4);
        p[k] = (b2 ? p[k + 2] : p[k]) + recv;
    }
    const bool b3 = lane & 8;
    {
        float send = b3 ? p[0] : p[1];
        float recv = __shfl_xor_sync(FULL, send, 8);
        p[0] = (b3 ? p[1] : p[0]) + recv;
    }
    p[0] += __shfl_xor_sync(FULL, p[0], 16);
    const int l4  = lane & 15;
    const int rev = ((l4 & 1) << 3) | ((l4 & 2) << 1) | ((l4 & 4) >> 1) | ((l4 & 8) >> 3);
    return __shfl_sync(FULL, p[0], rev);
}

__device__ __forceinline__ void diff_sq(const float4& yi, const float4& v, float& outv) {
    float dx = yi.x - v.x, dy = yi.y - v.y;
    float dz = yi.z - v.z, dw = yi.w - v.w;
    outv = dx * dx + dy * dy + dz * dz + dw * dw;
}

__device__ __forceinline__ void finish_and_write(
    float s, bool sel, int lane, int i, int mycol,
    float* __restrict__ out, int N, int topk)
{
    unsigned bal = __ballot_sync(FULL, sel);
    float smax = sel ? s : -CUDART_INF_F;
#pragma unroll
    for (int o = 8; o > 0; o >>= 1)
        smax = fmaxf(smax, __shfl_xor_sync(FULL, smax, o));
    float e = sel ? expf(s - smax) : 0.f;
    float esum = e;
#pragma unroll
    for (int o = 8; o > 0; o >>= 1)
        esum += __shfl_xor_sync(FULL, esum, o);
    if (sel) {
        float w = e / esum;
        int k = __popc(bal & ((1u << lane) - 1u));
        size_t NT = (size_t)N * topk;
        size_t base = (size_t)i * topk + k;
        out[base]          = (float)i;
        out[NT + base]     = (float)mycol;
        out[2 * NT + base] = w;
    }
}

// ---------------------------------------------------------------------------
// Edge kernel (fast shape): MMA-y scores; small-margin nodes are flagged
// for exact repair and produce no output here.
// ---------------------------------------------------------------------------
__global__ __launch_bounds__(256, 5) void edge_kernel(
    const int* __restrict__ eidx, const float* __restrict__ logt,
    float* __restrict__ out, int N, int deg, int topk)
{
    const int warp = blockIdx.x * (blockDim.x >> 5) + (threadIdx.x >> 5);
    const int lane = threadIdx.x & 31;
    if (warp >= N) return;
    const int i = warp;

    const int* colp = eidx + (size_t)N * deg + (size_t)i * deg;
    int mycol = (lane < 16) ? colp[lane] : 0;

    const float rtemp = expf(-logt[0]);

    float4 yi = *(const float4*)(g_xp + (size_t)i * D_DIM + lane * 4);
    float p[16];
#pragma unroll
    for (int g = 0; g < 4; g++) {
        float4 v[4];
#pragma unroll
        for (int n = 0; n < 4; n++) {
            int c = __shfl_sync(FULL, mycol, g * 4 + n);
            v[n] = *(const float4*)(g_xp + (size_t)c * D_DIM + lane * 4);
        }
#pragma unroll
        for (int n = 0; n < 4; n++) diff_sq(yi, v[n], p[g * 4 + n]);
    }
    float raw = butterfly_score(p, lane);
    float s = (lane < 16) ? (-raw * rtemp) : -CUDART_INF_F;

    int rank = 0;
#pragma unroll
    for (int m = 0; m < 16; m++) {
        float sm = __shfl_sync(FULL, s, m);
        rank += (sm > s || (sm == s && m < lane)) ? 1 : 0;
    }
    bool sel = rank < topk;

    float m1 = sel ? s : CUDART_INF_F;
    float m2 = (!sel && lane < 16) ? s : -CUDART_INF_F;
#pragma unroll
    for (int o = 16; o > 0; o >>= 1) {
        m1 = fminf(m1, __shfl_xor_sync(FULL, m1, o));
        m2 = fmaxf(m2, __shfl_xor_sync(FULL, m2, o));
    }
    if (m1 - m2 < GAP_THRESH) {
        if (lane == 0) {
            int idx = atomicAdd(&g_nflag, 1);
            g_flag[idx] = i;
        }
        return;   // repair kernel owns this node's output
    }

    finish_and_write(s, sel, lane, i, mycol, out, N, topk);
}

// ---------------------------------------------------------------------------
// Repair kernel: one block per flagged node, smem-staged and conflict-free.
// Blocks with no work exit before staging W.
// ---------------------------------------------------------------------------
#define RW_PITCH 129
#define REPAIR_SMEM_FLOATS (128 * RW_PITCH + 2176 + 2176 + 128)

__global__ __launch_bounds__(256) void repair_kernel(
    const int* __restrict__ eidx, const float* __restrict__ logt,
    const float* __restrict__ X, const float* __restrict__ W,
    const float* __restrict__ logd,
    float* __restrict__ out, int N, int deg, int topk)
{
    extern __shared__ float rsm[];
    float* Ws = rsm;
    float* Xs = rsm + 128 * RW_PITCH;
    float* ys = Xs + 17 * 128;
    float* sc = ys + 17 * 128;
    __shared__ int cols_s[17];

    const int tid = threadIdx.x;
    const int nf = g_nflag;
    if ((int)blockIdx.x >= nf) return;   // no work: skip W staging entirely

    // stage W (once per block): coalesced float4 reads
    for (int t = tid; t < 128 * 32; t += 256) {
        int c  = t >> 5;
        int kq = (t & 31) * 4;
        float4 wv = *(const float4*)(W + (size_t)c * D_DIM + kq);
        Ws[c * RW_PITCH + kq + 0] = wv.x;
        Ws[c * RW_PITCH + kq + 1] = wv.y;
        Ws[c * RW_PITCH + kq + 2] = wv.z;
        Ws[c * RW_PITCH + kq + 3] = wv.w;
    }
    if (tid < 128) {
        float ld = logd[tid];
        float sp = (ld > 20.f) ? ld : log1pf(expf(ld));
        sc[tid] = sqrtf(sp + EPS_F);
    }

    for (int f = blockIdx.x; f < nf; f += gridDim.x) {
        __syncthreads();
        const int i = g_flag[f];
        if (tid < 16) cols_s[tid] = eidx[(size_t)N * deg + (size_t)i * deg + tid];
        if (tid == 16) cols_s[16] = i;
        __syncthreads();

        for (int t = tid; t < 17 * 32; t += 256) {
            int r  = t >> 5;
            int kq = (t & 31) * 4;
            int row = cols_s[r];
            float4 xv = *(const float4*)(X + (size_t)row * D_DIM + kq);
            *(float4*)(Xs + r * 128 + kq) = xv;
        }
        __syncthreads();

        const int c  = tid & 127;
        const int rp = tid >> 7;
        const float* wr = Ws + c * RW_PITCH;
        const float scv = sc[c];
#pragma unroll
        for (int gg = 0; gg < 5; gg++) {
            int rA = rp + 4 * gg;
            int rB = rp + 4 * gg + 2;
            bool hA = rA < 17, hB = rB < 17;
            const float* xA = Xs + (hA ? rA : 0) * 128;
            const float* xB = Xs + (hB ? rB : 0) * 128;
            float a = 0.f, b = 0.f;
#pragma unroll 16
            for (int k = 0; k < D_DIM; k++) {
                float wv = wr[k];
                a = fmaf(xA[k], wv, a);
                b = fmaf(xB[k], wv, b);
            }
            if (hA) ys[rA * 128 + c] = a * scv;
            if (hB) ys[rB * 128 + c] = b * scv;
        }
        __syncthreads();

        if (tid < 32) {
            const int lane = tid;
            int mycol = (lane < 16) ? cols_s[lane] : 0;
            const float rtemp = expf(-logt[0]);
            float4 yi = *(const float4*)(ys + 16 * 128 + lane * 4);
            float p[16];
#pragma unroll
            for (int n = 0; n < 16; n++) {
                float4 v = *(const float4*)(ys + n * 128 + lane * 4);
                diff_sq(yi, v, p[n]);
            }
            float rawv = butterfly_score(p, lane);
            float s = (lane < 16) ? (-rawv * rtemp) : -CUDART_INF_F;
            int rank = 0;
#pragma unroll
            for (int m = 0; m < 16; m++) {
                float sm = __shfl_sync(FULL, s, m);
                rank += (sm > s || (sm == s && m < lane)) ? 1 : 0;
            }
            bool sel = rank < topk;
            finish_and_write(s, sel, lane, i, mycol, out, N, topk);
        }
    }
}

// ---------------------------------------------------------------------------
extern "C" void kernel_launch(void* const* d_in, const int* in_sizes, int n_in,
                              void* d_out, int out_size)
{
    const float* x    = (const float*)d_in[0];
    const int*   eidx = (const int*)  d_in[1];
    const float* W    = (const float*)d_in[2];
    const float* logd = (const float*)d_in[3];
    const float* logt = (const float*)d_in[4];

    const int D   = 128;
    const int N   = in_sizes[0] / D;
    const int deg = in_sizes[1] / (2 * N);
    const int topk = out_size / (3 * N);

    float* out = (float*)d_out;

    const int smem_bytes = (128 + 4 * BUF_FLOATS) * sizeof(float);
    cudaFuncSetAttribute(proj_mma_kernel,
                         cudaFuncAttributeMaxDynamicSharedMemorySize, smem_bytes);
    proj_mma_kernel<<<(N + 127) / 128, 512, smem_bytes>>>(x, W, logd, N);

    int warps_per_block = 256 / 32;
    int blocks = (N + warps_per_block - 1) / warps_per_block;
    edge_kernel<<<blocks, 256>>>(eidx, logt, out, N, deg, topk);

    const int repair_smem = REPAIR_SMEM_FLOATS * sizeof(float);
    cudaFuncSetAttribute(repair_kernel,
                         cudaFuncAttributeMaxDynamicSharedMemorySize, repair_smem);
    repair_kernel<<<148, 256, repair_smem>>>(eidx, logt, x, W, logd, out, N, deg, topk);
}

// round 16
// speedup vs baseline: 3.9179x; 1.0367x over previous
#include <cuda_runtime.h>
#include <math.h>
#include <math_constants.h>

#define D_DIM 128
#define MAXN  50048
#define EPS_F 1e-8f
#define FULL  0xffffffffu
#define GAP_THRESH 1e-3f

typedef unsigned int u32;

__device__ float g_xp[(size_t)MAXN * D_DIM];
__device__ int   g_flag[MAXN];
__device__ int   g_nflag;
__device__ u32   g_whi[D_DIM * D_DIM];
__device__ u32   g_wlo[D_DIM * D_DIM];

// ---------------------------------------------------------------------------
// tf32 helpers
// ---------------------------------------------------------------------------
__device__ __forceinline__ u32 to_tf32(float x) {
    u32 r; asm("cvt.rna.tf32.f32 %0, %1;" : "=r"(r) : "f"(x)); return r;
}
__device__ __forceinline__ void split_tf32(float x, u32& hi, u32& lo) {
    hi = to_tf32(x);
    float rem = x - __uint_as_float(hi);
    lo = to_tf32(rem);
}
__device__ __forceinline__ void mma_tf32(float* c, const u32* a, const u32* b) {
    asm volatile(
        "mma.sync.aligned.m16n8k8.row.col.f32.tf32.tf32.f32 "
        "{%0,%1,%2,%3}, {%4,%5,%6,%7}, {%8,%9}, {%0,%1,%2,%3};"
        : "+f"(c[0]), "+f"(c[1]), "+f"(c[2]), "+f"(c[3])
        : "r"(a[0]), "r"(a[1]), "r"(a[2]), "r"(a[3]), "r"(b[0]), "r"(b[1]));
}

#define KC      32
#define XPITCH  36
#define WPITCH  132
#define XBUF_FLOATS (128 * XPITCH)
// smem: scale 128 | WhiF 128*132 | WloF 128*132 | 2 x (Xhi + Xlo) chunk bufs
#define SMEM_FLOATS (128 + 2 * 128 * WPITCH + 4 * XBUF_FLOATS)

// ---------------------------------------------------------------------------
// W pre-split kernel: one-time exact split of W into tf32 hi/lo globals.
// ---------------------------------------------------------------------------
__global__ void split_w_kernel(const float* __restrict__ W) {
    int t = blockIdx.x * blockDim.x + threadIdx.x;
    if (t < D_DIM * D_DIM) {
        u32 h, l;
        split_tf32(W[t], h, l);
        g_whi[t] = h;
        g_wlo[t] = l;
    }
}

// ---------------------------------------------------------------------------
// Projection: Y = (X @ W^T) * sqrt(softplus(logd)+eps), 3-pass split-TF32,
// pipelined: W (pre-split) staged once per block; X chunks double-buffered
// with register prefetch; ONE __syncthreads per K-chunk.
// Residual ~2e-5 score noise is caught by the margin check + repair kernel.
// ---------------------------------------------------------------------------
__global__ __launch_bounds__(512, 1) void proj_mma_kernel(
    const float* __restrict__ X, const float* __restrict__ logd, int N)
{
    extern __shared__ float smem[];
    float* scale = smem;                         // 128
    float* WhiF  = smem + 128;                   // 128*132
    float* WloF  = WhiF + 128 * WPITCH;          // 128*132
    float* Xbuf  = WloF + 128 * WPITCH;          // 2 x (Xhi+Xlo)

    const int tid  = threadIdx.x;
    const int lane = tid & 31;
    const int wid  = tid >> 5;
    const int wm   = wid & 3;
    const int wn   = wid >> 2;
    const int m0   = blockIdx.x * 128;

    if (blockIdx.x == 0 && tid == 0) g_nflag = 0;

    if (tid < 128) {
        float ld = logd[tid];
        float sp = (ld > 20.f) ? ld : log1pf(expf(ld));
        scale[tid] = sqrtf(sp + EPS_F);
    }

    // stage full pre-split W: 128 rows x 32 uint4/row = 4096 uint4 total
#pragma unroll
    for (int j = 0; j < 8; j++) {
        int idx  = tid + j * 512;                // 0..4095 (uint4 index)
        int n    = idx >> 5;                     // row 0..127
        int koff = (idx & 31) * 4;               // u32 offset within row 0..124
        uint4 hv = *(const uint4*)(g_whi + n * 128 + koff);
        uint4 lv = *(const uint4*)(g_wlo + n * 128 + koff);
        *(uint4*)((u32*)WhiF + n * WPITCH + koff) = hv;
        *(uint4*)((u32*)WloF + n * WPITCH + koff) = lv;
    }

    float acc[2][4][4];
#pragma unroll
    for (int mt = 0; mt < 2; mt++)
#pragma unroll
        for (int nt = 0; nt < 4; nt++)
#pragma unroll
            for (int q = 0; q < 4; q++) acc[mt][nt][q] = 0.f;

    const int fr = lane >> 2;
    const int fc = lane & 3;
    const int xr0 = tid >> 3;                    // row for prefetch slot 0 (0..63)
    const int xk4 = (tid & 7) * 4;               // k offset within chunk

    // prefetch chunk 0
    float4 pf[2];
    {
        int gr0 = m0 + xr0, gr1 = m0 + xr0 + 64;
        pf[0] = (gr0 < N) ? *(const float4*)(X + (size_t)gr0 * D_DIM + xk4)
                          : make_float4(0.f, 0.f, 0.f, 0.f);
        pf[1] = (gr1 < N) ? *(const float4*)(X + (size_t)gr1 * D_DIM + xk4)
                          : make_float4(0.f, 0.f, 0.f, 0.f);
    }

    for (int kt = 0; kt < 4; kt++) {
        float* Xhi = Xbuf + (kt & 1) * (2 * XBUF_FLOATS);
        float* Xlo = Xhi + XBUF_FLOATS;

        // split + store prefetched X chunk
#pragma unroll
        for (int it = 0; it < 2; it++) {
            int r = xr0 + it * 64;
            u32 h0, l0, h1, l1, h2, l2, h3, l3;
            split_tf32(pf[it].x, h0, l0); split_tf32(pf[it].y, h1, l1);
            split_tf32(pf[it].z, h2, l2); split_tf32(pf[it].w, h3, l3);
            u32* xh = (u32*)(Xhi + r * XPITCH + xk4);
            u32* xl = (u32*)(Xlo + r * XPITCH + xk4);
            xh[0] = h0; xh[1] = h1; xh[2] = h2; xh[3] = h3;
            xl[0] = l0; xl[1] = l1; xl[2] = l2; xl[3] = l3;
        }
        __syncthreads();

        // prefetch next chunk (LDG latency hides under the MMAs below)
        if (kt < 3) {
            int gr0 = m0 + xr0, gr1 = m0 + xr0 + 64;
            int kb = (kt + 1) * KC + xk4;
            pf[0] = (gr0 < N) ? *(const float4*)(X + (size_t)gr0 * D_DIM + kb)
                              : make_float4(0.f, 0.f, 0.f, 0.f);
            pf[1] = (gr1 < N) ? *(const float4*)(X + (size_t)gr1 * D_DIM + kb)
                              : make_float4(0.f, 0.f, 0.f, 0.f);
        }

#pragma unroll
        for (int ks = 0; ks < KC / 8; ks++) {
            u32 ah[2][4], al[2][4];
#pragma unroll
            for (int mt = 0; mt < 2; mt++) {
                int rb = (wm * 32 + mt * 16 + fr) * XPITCH + ks * 8 + fc;
                ah[mt][0] = *(u32*)(Xhi + rb);
                ah[mt][1] = *(u32*)(Xhi + rb + 8 * XPITCH);
                ah[mt][2] = *(u32*)(Xhi + rb + 4);
                ah[mt][3] = *(u32*)(Xhi + rb + 8 * XPITCH + 4);
                al[mt][0] = *(u32*)(Xlo + rb);
                al[mt][1] = *(u32*)(Xlo + rb + 8 * XPITCH);
                al[mt][2] = *(u32*)(Xlo + rb + 4);
                al[mt][3] = *(u32*)(Xlo + rb + 8 * XPITCH + 4);
            }
            u32 bh[4][2], bl[4][2];
#pragma unroll
            for (int nt = 0; nt < 4; nt++) {
                int nb = (wn * 32 + nt * 8 + fr) * WPITCH + kt * KC + ks * 8 + fc;
                bh[nt][0] = *(u32*)(WhiF + nb);
                bh[nt][1] = *(u32*)(WhiF + nb + 4);
                bl[nt][0] = *(u32*)(WloF + nb);
                bl[nt][1] = *(u32*)(WloF + nb + 4);
            }
#pragma unroll
            for (int mt = 0; mt < 2; mt++)
#pragma unroll
                for (int nt = 0; nt < 4; nt++) {
                    mma_tf32(acc[mt][nt], ah[mt], bh[nt]);
                    mma_tf32(acc[mt][nt], ah[mt], bl[nt]);
                    mma_tf32(acc[mt][nt], al[mt], bh[nt]);
                }
        }
    }

#pragma unroll
    for (int mt = 0; mt < 2; mt++) {
        int row0 = m0 + wm * 32 + mt * 16 + fr;
#pragma unroll
        for (int nt = 0; nt < 4; nt++) {
            int col = wn * 32 + nt * 8 + 2 * fc;
            float s0 = scale[col], s1 = scale[col + 1];
            if (row0 < N) {
                float2 o0 = make_float2(acc[mt][nt][0] * s0, acc[mt][nt][1] * s1);
                *(float2*)(g_xp + (size_t)row0 * D_DIM + col) = o0;
            }
            if (row0 + 8 < N) {
                float2 o1 = make_float2(acc[mt][nt][2] * s0, acc[mt][nt][3] * s1);
                *(float2*)(g_xp + (size_t)(row0 + 8) * D_DIM + col) = o1;
            }
        }
    }
}

// ---------------------------------------------------------------------------
// Shared warp-level machinery (identical realization in edge + repair)
// ---------------------------------------------------------------------------
__device__ __forceinline__ float butterfly_score(float* p, int lane) {
    const bool b0 = lane & 1;
#pragma unroll
    for (int k = 0; k < 8; k++) {
        float send = b0 ? p[k] : p[k + 8];
        float recv = __shfl_xor_sync(FULL, send, 1);
        p[k] = (b0 ? p[k + 8] : p[k]) + recv;
    }
    const bool b1 = lane & 2;
#pragma unroll
    for (int k = 0; k < 4; k++) {
        float send = b1 ? p[k] : p[k + 4];
        float recv = __shfl_xor_sync(FULL, send, 2);
        p[k] = (b1 ? p[k + 4] : p[k]) + recv;
    }
    const bool b2 = lane & 4;
#pragma unroll
    for (int k = 0; k < 2; k++) {
        float send = b2 ? p[k] : p[k + 2];
        float recv = __shfl_xor_sync(FULL, send, 4);
        p[k] = (b2 ? p[k + 2] : p[k]) + recv;
    }
    const bool b3 = lane & 8;
    {
        float send = b3 ? p[0] : p[1];
        float recv = __shfl_xor_sync(FULL, send, 8);
        p[0] = (b3 ? p[1] : p[0]) + recv;
    }
    p[0] += __shfl_xor_sync(FULL, p[0], 16);
    const int l4  = lane & 15;
    const int rev = ((l4 & 1) << 3) | ((l4 & 2) << 1) | ((l4 & 4) >> 1) | ((l4 & 8) >> 3);
    return __shfl_sync(FULL, p[0], rev);
}

__device__ __forceinline__ void diff_sq(const float4& yi, const float4& v, float& outv) {
    float dx = yi.x - v.x, dy = yi.y - v.y;
    float dz = yi.z - v.z, dw = yi.w - v.w;
    outv = dx * dx + dy * dy + dz * dz + dw * dw;
}

__device__ __forceinline__ void finish_and_write(
    float s, bool sel, int lane, int i, int mycol,
    float* __restrict__ out, int N, int topk)
{
    unsigned bal = __ballot_sync(FULL, sel);
    float smax = sel ? s : -CUDART_INF_F;
#pragma unroll
    for (int o = 8; o > 0; o >>= 1)
        smax = fmaxf(smax, __shfl_xor_sync(FULL, smax, o));
    float e = sel ? expf(s - smax) : 0.f;
    float esum = e;
#pragma unroll
    for (int o = 8; o > 0; o >>= 1)
        esum += __shfl_xor_sync(FULL, esum, o);
    if (sel) {
        float w = e / esum;
        int k = __popc(bal & ((1u << lane) - 1u));
        size_t NT = (size_t)N * topk;
        size_t base = (size_t)i * topk + k;
        out[base]          = (float)i;
        out[NT + base]     = (float)mycol;
        out[2 * NT + base] = w;
    }
}

// ---------------------------------------------------------------------------
// Edge kernel (fast shape): MMA-y scores; small-margin nodes are flagged
// for exact repair and produce no output here.
// ---------------------------------------------------------------------------
__global__ __launch_bounds__(256, 5) void edge_kernel(
    const int* __restrict__ eidx, const float* __restrict__ logt,
    float* __restrict__ out, int N, int deg, int topk)
{
    const int warp = blockIdx.x * (blockDim.x >> 5) + (threadIdx.x >> 5);
    const int lane = threadIdx.x & 31;
    if (warp >= N) return;
    const int i = warp;

    const int* colp = eidx + (size_t)N * deg + (size_t)i * deg;
    int mycol = (lane < 16) ? colp[lane] : 0;

    const float rtemp = expf(-logt[0]);

    float4 yi = *(const float4*)(g_xp + (size_t)i * D_DIM + lane * 4);
    float p[16];
#pragma unroll
    for (int g = 0; g < 4; g++) {
        float4 v[4];
#pragma unroll
        for (int n = 0; n < 4; n++) {
            int c = __shfl_sync(FULL, mycol, g * 4 + n);
            v[n] = *(const float4*)(g_xp + (size_t)c * D_DIM + lane * 4);
        }
#pragma unroll
        for (int n = 0; n < 4; n++) diff_sq(yi, v[n], p[g * 4 + n]);
    }
    float raw = butterfly_score(p, lane);
    float s = (lane < 16) ? (-raw * rtemp) : -CUDART_INF_F;

    int rank = 0;
#pragma unroll
    for (int m = 0; m < 16; m++) {
        float sm = __shfl_sync(FULL, s, m);
        rank += (sm > s || (sm == s && m < lane)) ? 1 : 0;
    }
    bool sel = rank < topk;

    float m1 = sel ? s : CUDART_INF_F;
    float m2 = (!sel && lane < 16) ? s : -CUDART_INF_F;
#pragma unroll
    for (int o = 16; o > 0; o >>= 1) {
        m1 = fminf(m1, __shfl_xor_sync(FULL, m1, o));
        m2 = fmaxf(m2, __shfl_xor_sync(FULL, m2, o));
    }
    if (m1 - m2 < GAP_THRESH) {
        if (lane == 0) {
            int idx = atomicAdd(&g_nflag, 1);
            g_flag[idx] = i;
        }
        return;   // repair kernel owns this node's output
    }

    finish_and_write(s, sel, lane, i, mycol, out, N, topk);
}

// ---------------------------------------------------------------------------
// Repair kernel: one block per flagged node, smem-staged and conflict-free.
// Blocks with no work exit before staging W.
// ---------------------------------------------------------------------------
#define RW_PITCH 129
#define REPAIR_SMEM_FLOATS (128 * RW_PITCH + 2176 + 2176 + 128)

__global__ __launch_bounds__(256) void repair_kernel(
    const int* __restrict__ eidx, const float* __restrict__ logt,
    const float* __restrict__ X, const float* __restrict__ W,
    const float* __restrict__ logd,
    float* __restrict__ out, int N, int deg, int topk)
{
    extern __shared__ float rsm[];
    float* Ws = rsm;
    float* Xs = rsm + 128 * RW_PITCH;
    float* ys = Xs + 17 * 128;
    float* sc = ys + 17 * 128;
    __shared__ int cols_s[17];

    const int tid = threadIdx.x;
    const int nf = g_nflag;
    if ((int)blockIdx.x >= nf) return;

    for (int t = tid; t < 128 * 32; t += 256) {
        int c  = t >> 5;
        int kq = (t & 31) * 4;
        float4 wv = *(const float4*)(W + (size_t)c * D_DIM + kq);
        Ws[c * RW_PITCH + kq + 0] = wv.x;
        Ws[c * RW_PITCH + kq + 1] = wv.y;
        Ws[c * RW_PITCH + kq + 2] = wv.z;
        Ws[c * RW_PITCH + kq + 3] = wv.w;
    }
    if (tid < 128) {
        float ld = logd[tid];
        float sp = (ld > 20.f) ? ld : log1pf(expf(ld));
        sc[tid] = sqrtf(sp + EPS_F);
    }

    for (int f = blockIdx.x; f < nf; f += gridDim.x) {
        __syncthreads();
        const int i = g_flag[f];
        if (tid < 16) cols_s[tid] = eidx[(size_t)N * deg + (size_t)i * deg + tid];
        if (tid == 16) cols_s[16] = i;
        __syncthreads();

        for (int t = tid; t < 17 * 32; t += 256) {
            int r  = t >> 5;
            int kq = (t & 31) * 4;
            int row = cols_s[r];
            float4 xv = *(const float4*)(X + (size_t)row * D_DIM + kq);
            *(float4*)(Xs + r * 128 + kq) = xv;
        }
        __syncthreads();

        const int c  = tid & 127;
        const int rp = tid >> 7;
        const float* wr = Ws + c * RW_PITCH;
        const float scv = sc[c];
#pragma unroll
        for (int gg = 0; gg < 5; gg++) {
            int rA = rp + 4 * gg;
            int rB = rp + 4 * gg + 2;
            bool hA = rA < 17, hB = rB < 17;
            const float* xA = Xs + (hA ? rA : 0) * 128;
            const float* xB = Xs + (hB ? rB : 0) * 128;
            float a = 0.f, b = 0.f;
#pragma unroll 16
            for (int k = 0; k < D_DIM; k++) {
                float wv = wr[k];
                a = fmaf(xA[k], wv, a);
                b = fmaf(xB[k], wv, b);
            }
            if (hA) ys[rA * 128 + c] = a * scv;
            if (hB) ys[rB * 128 + c] = b * scv;
        }
        __syncthreads();

        if (tid < 32) {
            const int lane = tid;
            int mycol = (lane < 16) ? cols_s[lane] : 0;
            const float rtemp = expf(-logt[0]);
            float4 yi = *(const float4*)(ys + 16 * 128 + lane * 4);
            float p[16];
#pragma unroll
            for (int n = 0; n < 16; n++) {
                float4 v = *(const float4*)(ys + n * 128 + lane * 4);
                diff_sq(yi, v, p[n]);
            }
            float rawv = butterfly_score(p, lane);
            float s = (lane < 16) ? (-rawv * rtemp) : -CUDART_INF_F;
            int rank = 0;
#pragma unroll
            for (int m = 0; m < 16; m++) {
                float sm = __shfl_sync(FULL, s, m);
                rank += (sm > s || (sm == s && m < lane)) ? 1 : 0;
            }
            bool sel = rank < topk;
            finish_and_write(s, sel, lane, i, mycol, out, N, topk);
        }
    }
}

// ---------------------------------------------------------------------------
extern "C" void kernel_launch(void* const* d_in, const int* in_sizes, int n_in,
                              void* d_out, int out_size)
{
    const float* x    = (const float*)d_in[0];
    const int*   eidx = (const int*)  d_in[1];
    const float* W    = (const float*)d_in[2];
    const float* logd = (const float*)d_in[3];
    const float* logt = (const float*)d_in[4];

    const int D   = 128;
    const int N   = in_sizes[0] / D;
    const int deg = in_sizes[1] / (2 * N);
    const int topk = out_size / (3 * N);

    float* out = (float*)d_out;

    split_w_kernel<<<32, 512>>>(W);

    const int smem_bytes = SMEM_FLOATS * sizeof(float);   // ~209 KB
    cudaFuncSetAttribute(proj_mma_kernel,
                         cudaFuncAttributeMaxDynamicSharedMemorySize, smem_bytes);
    proj_mma_kernel<<<(N + 127) / 128, 512, smem_bytes>>>(x, logd, N);

    int warps_per_block = 256 / 32;
    int blocks = (N + warps_per_block - 1) / warps_per_block;
    edge_kernel<<<blocks, 256>>>(eidx, logt, out, N, deg, topk);

    const int repair_smem = REPAIR_SMEM_FLOATS * sizeof(float);
    cudaFuncSetAttribute(repair_kernel,
                         cudaFuncAttributeMaxDynamicSharedMemorySize, repair_smem);
    repair_kernel<<<148, 256, repair_smem>>>(eidx, logt, x, W, logd, out, N, deg, topk);
}

// round 17
// speedup vs baseline: 3.9521x; 1.0087x over previous
#include <cuda_runtime.h>
#include <math.h>
#include <math_constants.h>

#define D_DIM 128
#define MAXN  50048
#define EPS_F 1e-8f
#define FULL  0xffffffffu
#define GAP_THRESH 1e-3f

typedef unsigned int u32;

__device__ float g_xp[(size_t)MAXN * D_DIM];
__device__ int   g_flag[MAXN];
__device__ int   g_nflag;
__device__ u32   g_whi[D_DIM * D_DIM];
__device__ u32   g_wlo[D_DIM * D_DIM];

// ---------------------------------------------------------------------------
// Exact bit-split: hi = x with low 13 mantissa bits cleared (exactly
// tf32-representable, same layout cvt.rna.tf32 emits); lo = x - hi (exact
// fp32; HMMA reads the top 19 bits of the operand register, truncating the
// rest). 2 ops (LOP3 + FADD), no cvt.
// ---------------------------------------------------------------------------
__device__ __forceinline__ void split_trunc(float x, u32& hi, u32& lo) {
    u32 xb = __float_as_uint(x);
    hi = xb & 0xFFFFE000u;
    lo = __float_as_uint(x - __uint_as_float(hi));
}
__device__ __forceinline__ void mma_tf32(float* c, const u32* a, const u32* b) {
    asm volatile(
        "mma.sync.aligned.m16n8k8.row.col.f32.tf32.tf32.f32 "
        "{%0,%1,%2,%3}, {%4,%5,%6,%7}, {%8,%9}, {%0,%1,%2,%3};"
        : "+f"(c[0]), "+f"(c[1]), "+f"(c[2]), "+f"(c[3])
        : "r"(a[0]), "r"(a[1]), "r"(a[2]), "r"(a[3]), "r"(b[0]), "r"(b[1]));
}

#define KC      32
#define XPITCH  36
#define WPITCH  132
#define XBUF_FLOATS (128 * XPITCH)
// smem: scale 128 | WhiF 128*132 | WloF 128*132 | 2 x (Xhi + Xlo) chunk bufs
#define SMEM_FLOATS (128 + 2 * 128 * WPITCH + 4 * XBUF_FLOATS)

// ---------------------------------------------------------------------------
// W pre-split kernel: one-time exact bit-split of W into hi/lo globals.
// ---------------------------------------------------------------------------
__global__ void split_w_kernel(const float* __restrict__ W) {
    int t = blockIdx.x * blockDim.x + threadIdx.x;
    if (t < D_DIM * D_DIM) {
        u32 h, l;
        split_trunc(W[t], h, l);
        g_whi[t] = h;
        g_wlo[t] = l;
    }
}

// ---------------------------------------------------------------------------
// Projection: Y = (X @ W^T) * sqrt(softplus(logd)+eps), 3-pass split-TF32,
// pipelined: W (pre-split) staged once per block; X chunks double-buffered
// with register prefetch; ONE __syncthreads per K-chunk; cvt-free bit-split.
// Residual ~2e-5 score noise is caught by the margin check + repair kernel.
// ---------------------------------------------------------------------------
__global__ __launch_bounds__(512, 1) void proj_mma_kernel(
    const float* __restrict__ X, const float* __restrict__ logd, int N)
{
    extern __shared__ float smem[];
    float* scale = smem;                         // 128
    float* WhiF  = smem + 128;                   // 128*132
    float* WloF  = WhiF + 128 * WPITCH;          // 128*132
    float* Xbuf  = WloF + 128 * WPITCH;          // 2 x (Xhi+Xlo)

    const int tid  = threadIdx.x;
    const int lane = tid & 31;
    const int wid  = tid >> 5;
    const int wm   = wid & 3;
    const int wn   = wid >> 2;
    const int m0   = blockIdx.x * 128;

    if (blockIdx.x == 0 && tid == 0) g_nflag = 0;

    if (tid < 128) {
        float ld = logd[tid];
        float sp = (ld > 20.f) ? ld : log1pf(expf(ld));
        scale[tid] = sqrtf(sp + EPS_F);
    }

    // stage full pre-split W: 128 rows x 32 uint4/row = 4096 uint4 total
#pragma unroll
    for (int j = 0; j < 8; j++) {
        int idx  = tid + j * 512;                // 0..4095 (uint4 index)
        int n    = idx >> 5;                     // row 0..127
        int koff = (idx & 31) * 4;               // u32 offset within row
        uint4 hv = *(const uint4*)(g_whi + n * 128 + koff);
        uint4 lv = *(const uint4*)(g_wlo + n * 128 + koff);
        *(uint4*)((u32*)WhiF + n * WPITCH + koff) = hv;
        *(uint4*)((u32*)WloF + n * WPITCH + koff) = lv;
    }

    float acc[2][4][4];
#pragma unroll
    for (int mt = 0; mt < 2; mt++)
#pragma unroll
        for (int nt = 0; nt < 4; nt++)
#pragma unroll
            for (int q = 0; q < 4; q++) acc[mt][nt][q] = 0.f;

    const int fr = lane >> 2;
    const int fc = lane & 3;
    const int xr0 = tid >> 3;                    // row for prefetch slot 0 (0..63)
    const int xk4 = (tid & 7) * 4;               // k offset within chunk

    // prefetch chunk 0
    float4 pf[2];
    {
        int gr0 = m0 + xr0, gr1 = m0 + xr0 + 64;
        pf[0] = (gr0 < N) ? *(const float4*)(X + (size_t)gr0 * D_DIM + xk4)
                          : make_float4(0.f, 0.f, 0.f, 0.f);
        pf[1] = (gr1 < N) ? *(const float4*)(X + (size_t)gr1 * D_DIM + xk4)
                          : make_float4(0.f, 0.f, 0.f, 0.f);
    }

    for (int kt = 0; kt < 4; kt++) {
        float* Xhi = Xbuf + (kt & 1) * (2 * XBUF_FLOATS);
        float* Xlo = Xhi + XBUF_FLOATS;

        // bit-split + STS.128 the prefetched X chunk
#pragma unroll
        for (int it = 0; it < 2; it++) {
            int r = xr0 + it * 64;
            u32 h0, l0, h1, l1, h2, l2, h3, l3;
            split_trunc(pf[it].x, h0, l0); split_trunc(pf[it].y, h1, l1);
            split_trunc(pf[it].z, h2, l2); split_trunc(pf[it].w, h3, l3);
            *(uint4*)(Xhi + r * XPITCH + xk4) = make_uint4(h0, h1, h2, h3);
            *(uint4*)(Xlo + r * XPITCH + xk4) = make_uint4(l0, l1, l2, l3);
        }
        __syncthreads();

        // prefetch next chunk (LDG latency hides under the MMAs below)
        if (kt < 3) {
            int gr0 = m0 + xr0, gr1 = m0 + xr0 + 64;
            int kb = (kt + 1) * KC + xk4;
            pf[0] = (gr0 < N) ? *(const float4*)(X + (size_t)gr0 * D_DIM + kb)
                              : make_float4(0.f, 0.f, 0.f, 0.f);
            pf[1] = (gr1 < N) ? *(const float4*)(X + (size_t)gr1 * D_DIM + kb)
                              : make_float4(0.f, 0.f, 0.f, 0.f);
        }

#pragma unroll
        for (int ks = 0; ks < KC / 8; ks++) {
            u32 ah[2][4], al[2][4];
#pragma unroll
            for (int mt = 0; mt < 2; mt++) {
                int rb = (wm * 32 + mt * 16 + fr) * XPITCH + ks * 8 + fc;
                ah[mt][0] = *(u32*)(Xhi + rb);
                ah[mt][1] = *(u32*)(Xhi + rb + 8 * XPITCH);
                ah[mt][2] = *(u32*)(Xhi + rb + 4);
                ah[mt][3] = *(u32*)(Xhi + rb + 8 * XPITCH + 4);
                al[mt][0] = *(u32*)(Xlo + rb);
                al[mt][1] = *(u32*)(Xlo + rb + 8 * XPITCH);
                al[mt][2] = *(u32*)(Xlo + rb + 4);
                al[mt][3] = *(u32*)(Xlo + rb + 8 * XPITCH + 4);
            }
            u32 bh[4][2], bl[4][2];
#pragma unroll
            for (int nt = 0; nt < 4; nt++) {
                int nb = (wn * 32 + nt * 8 + fr) * WPITCH + kt * KC + ks * 8 + fc;
                bh[nt][0] = *(u32*)(WhiF + nb);
                bh[nt][1] = *(u32*)(WhiF + nb + 4);
                bl[nt][0] = *(u32*)(WloF + nb);
                bl[nt][1] = *(u32*)(WloF + nb + 4);
            }
#pragma unroll
            for (int mt = 0; mt < 2; mt++)
#pragma unroll
                for (int nt = 0; nt < 4; nt++) {
                    mma_tf32(acc[mt][nt], ah[mt], bh[nt]);
                    mma_tf32(acc[mt][nt], ah[mt], bl[nt]);
                    mma_tf32(acc[mt][nt], al[mt], bh[nt]);
                }
        }
    }

#pragma unroll
    for (int mt = 0; mt < 2; mt++) {
        int row0 = m0 + wm * 32 + mt * 16 + fr;
#pragma unroll
        for (int nt = 0; nt < 4; nt++) {
            int col = wn * 32 + nt * 8 + 2 * fc;
            float s0 = scale[col], s1 = scale[col + 1];
            if (row0 < N) {
                float2 o0 = make_float2(acc[mt][nt][0] * s0, acc[mt][nt][1] * s1);
                *(float2*)(g_xp + (size_t)row0 * D_DIM + col) = o0;
            }
            if (row0 + 8 < N) {
                float2 o1 = make_float2(acc[mt][nt][2] * s0, acc[mt][nt][3] * s1);
                *(float2*)(g_xp + (size_t)(row0 + 8) * D_DIM + col) = o1;
            }
        }
    }
}

// ---------------------------------------------------------------------------
// Shared warp-level machinery (identical realization in edge + repair)
// ---------------------------------------------------------------------------
__device__ __forceinline__ float butterfly_score(float* p, int lane) {
    const bool b0 = lane & 1;
#pragma unroll
    for (int k = 0; k < 8; k++) {
        float send = b0 ? p[k] : p[k + 8];
        float recv = __shfl_xor_sync(FULL, send, 1);
        p[k] = (b0 ? p[k + 8] : p[k]) + recv;
    }
    const bool b1 = lane & 2;
#pragma unroll
    for (int k = 0; k < 4; k++) {
        float send = b1 ? p[k] : p[k + 4];
        float recv = __shfl_xor_sync(FULL, send, 2);
        p[k] = (b1 ? p[k + 4] : p[k]) + recv;
    }
    const bool b2 = lane & 4;
#pragma unroll
    for (int k = 0; k < 2; k++) {
        float send = b2 ? p[k] : p[k + 2];
        float recv = __shfl_xor_sync(FULL, send, 4);
        p[k] = (b2 ? p[k + 2] : p[k]) + recv;
    }
    const bool b3 = lane & 8;
    {
        float send = b3 ? p[0] : p[1];
        float recv = __shfl_xor_sync(FULL, send, 8);
        p[0] = (b3 ? p[1] : p[0]) + recv;
    }
    p[0] += __shfl_xor_sync(FULL, p[0], 16);
    const int l4  = lane & 15;
    const int rev = ((l4 & 1) << 3) | ((l4 & 2) << 1) | ((l4 & 4) >> 1) | ((l4 & 8) >> 3);
    return __shfl_sync(FULL, p[0], rev);
}

__device__ __forceinline__ void diff_sq(const float4& yi, const float4& v, float& outv) {
    float dx = yi.x - v.x, dy = yi.y - v.y;
    float dz = yi.z - v.z, dw = yi.w - v.w;
    outv = dx * dx + dy * dy + dz * dz + dw * dw;
}

__device__ __forceinline__ void finish_and_write(
    float s, bool sel, int lane, int i, int mycol,
    float* __restrict__ out, int N, int topk)
{
    unsigned bal = __ballot_sync(FULL, sel);
    float smax = sel ? s : -CUDART_INF_F;
#pragma unroll
    for (int o = 8; o > 0; o >>= 1)
        smax = fmaxf(smax, __shfl_xor_sync(FULL, smax, o));
    float e = sel ? expf(s - smax) : 0.f;
    float esum = e;
#pragma unroll
    for (int o = 8; o > 0; o >>= 1)
        esum += __shfl_xor_sync(FULL, esum, o);
    if (sel) {
        float w = e / esum;
        int k = __popc(bal & ((1u << lane) - 1u));
        size_t NT = (size_t)N * topk;
        size_t base = (size_t)i * topk + k;
        out[base]          = (float)i;
        out[NT + base]     = (float)mycol;
        out[2 * NT + base] = w;
    }
}

// ---------------------------------------------------------------------------
// Edge kernel (fast shape): MMA-y scores; small-margin nodes are flagged
// for exact repair and produce no output here.
// ---------------------------------------------------------------------------
__global__ __launch_bounds__(256, 5) void edge_kernel(
    const int* __restrict__ eidx, const float* __restrict__ logt,
    float* __restrict__ out, int N, int deg, int topk)
{
    const int warp = blockIdx.x * (blockDim.x >> 5) + (threadIdx.x >> 5);
    const int lane = threadIdx.x & 31;
    if (warp >= N) return;
    const int i = warp;

    const int* colp = eidx + (size_t)N * deg + (size_t)i * deg;
    int mycol = (lane < 16) ? colp[lane] : 0;

    const float rtemp = expf(-logt[0]);

    float4 yi = *(const float4*)(g_xp + (size_t)i * D_DIM + lane * 4);
    float p[16];
#pragma unroll
    for (int g = 0; g < 4; g++) {
        float4 v[4];
#pragma unroll
        for (int n = 0; n < 4; n++) {
            int c = __shfl_sync(FULL, mycol, g * 4 + n);
            v[n] = *(const float4*)(g_xp + (size_t)c * D_DIM + lane * 4);
        }
#pragma unroll
        for (int n = 0; n < 4; n++) diff_sq(yi, v[n], p[g * 4 + n]);
    }
    float raw = butterfly_score(p, lane);
    float s = (lane < 16) ? (-raw * rtemp) : -CUDART_INF_F;

    int rank = 0;
#pragma unroll
    for (int m = 0; m < 16; m++) {
        float sm = __shfl_sync(FULL, s, m);
        rank += (sm > s || (sm == s && m < lane)) ? 1 : 0;
    }
    bool sel = rank < topk;

    float m1 = sel ? s : CUDART_INF_F;
    float m2 = (!sel && lane < 16) ? s : -CUDART_INF_F;
#pragma unroll
    for (int o = 16; o > 0; o >>= 1) {
        m1 = fminf(m1, __shfl_xor_sync(FULL, m1, o));
        m2 = fmaxf(m2, __shfl_xor_sync(FULL, m2, o));
    }
    if (m1 - m2 < GAP_THRESH) {
        if (lane == 0) {
            int idx = atomicAdd(&g_nflag, 1);
            g_flag[idx] = i;
        }
        return;   // repair kernel owns this node's output
    }

    finish_and_write(s, sel, lane, i, mycol, out, N, topk);
}

// ---------------------------------------------------------------------------
// Repair kernel: one block per flagged node, smem-staged and conflict-free.
// Blocks with no work exit before staging W.
// ---------------------------------------------------------------------------
#define RW_PITCH 129
#define REPAIR_SMEM_FLOATS (128 * RW_PITCH + 2176 + 2176 + 128)

__global__ __launch_bounds__(256) void repair_kernel(
    const int* __restrict__ eidx, const float* __restrict__ logt,
    const float* __restrict__ X, const float* __restrict__ W,
    const float* __restrict__ logd,
    float* __restrict__ out, int N, int deg, int topk)
{
    extern __shared__ float rsm[];
    float* Ws = rsm;
    float* Xs = rsm + 128 * RW_PITCH;
    float* ys = Xs + 17 * 128;
    float* sc = ys + 17 * 128;
    __shared__ int cols_s[17];

    const int tid = threadIdx.x;
    const int nf = g_nflag;
    if ((int)blockIdx.x >= nf) return;

    for (int t = tid; t < 128 * 32; t += 256) {
        int c  = t >> 5;
        int kq = (t & 31) * 4;
        float4 wv = *(const float4*)(W + (size_t)c * D_DIM + kq);
        Ws[c * RW_PITCH + kq + 0] = wv.x;
        Ws[c * RW_PITCH + kq + 1] = wv.y;
        Ws[c * RW_PITCH + kq + 2] = wv.z;
        Ws[c * RW_PITCH + kq + 3] = wv.w;
    }
    if (tid < 128) {
        float ld = logd[tid];
        float sp = (ld > 20.f) ? ld : log1pf(expf(ld));
        sc[tid] = sqrtf(sp + EPS_F);
    }

    for (int f = blockIdx.x; f < nf; f += gridDim.x) {
        __syncthreads();
        const int i = g_flag[f];
        if (tid < 16) cols_s[tid] = eidx[(size_t)N * deg + (size_t)i * deg + tid];
        if (tid == 16) cols_s[16] = i;
        __syncthreads();

        for (int t = tid; t < 17 * 32; t += 256) {
            int r  = t >> 5;
            int kq = (t & 31) * 4;
            int row = cols_s[r];
            float4 xv = *(const float4*)(X + (size_t)row * D_DIM + kq);
            *(float4*)(Xs + r * 128 + kq) = xv;
        }
        __syncthreads();

        const int c  = tid & 127;
        const int rp = tid >> 7;
        const float* wr = Ws + c * RW_PITCH;
        const float scv = sc[c];
#pragma unroll
        for (int gg = 0; gg < 5; gg++) {
            int rA = rp + 4 * gg;
            int rB = rp + 4 * gg + 2;
            bool hA = rA < 17, hB = rB < 17;
            const float* xA = Xs + (hA ? rA : 0) * 128;
            const float* xB = Xs + (hB ? rB : 0) * 128;
            float a = 0.f, b = 0.f;
#pragma unroll 16
            for (int k = 0; k < D_DIM; k++) {
                float wv = wr[k];
                a = fmaf(xA[k], wv, a);
                b = fmaf(xB[k], wv, b);
            }
            if (hA) ys[rA * 128 + c] = a * scv;
            if (hB) ys[rB * 128 + c] = b * scv;
        }
        __syncthreads();

        if (tid < 32) {
            const int lane = tid;
            int mycol = (lane < 16) ? cols_s[lane] : 0;
            const float rtemp = expf(-logt[0]);
            float4 yi = *(const float4*)(ys + 16 * 128 + lane * 4);
            float p[16];
#pragma unroll
            for (int n = 0; n < 16; n++) {
                float4 v = *(const float4*)(ys + n * 128 + lane * 4);
                diff_sq(yi, v, p[n]);
            }
            float rawv = butterfly_score(p, lane);
            float s = (lane < 16) ? (-rawv * rtemp) : -CUDART_INF_F;
            int rank = 0;
#pragma unroll
            for (int m = 0; m < 16; m++) {
                float sm = __shfl_sync(FULL, s, m);
                rank += (sm > s || (sm == s && m < lane)) ? 1 : 0;
            }
            bool sel = rank < topk;
            finish_and_write(s, sel, lane, i, mycol, out, N, topk);
        }
    }
}

// ---------------------------------------------------------------------------
extern "C" void kernel_launch(void* const* d_in, const int* in_sizes, int n_in,
                              void* d_out, int out_size)
{
    const float* x    = (const float*)d_in[0];
    const int*   eidx = (const int*)  d_in[1];
    const float* W    = (const float*)d_in[2];
    const float* logd = (const float*)d_in[3];
    const float* logt = (const float*)d_in[4];

    const int D   = 128;
    const int N   = in_sizes[0] / D;
    const int deg = in_sizes[1] / (2 * N);
    const int topk = out_size / (3 * N);

    float* out = (float*)d_out;

    split_w_kernel<<<32, 512>>>(W);

    const int smem_bytes = SMEM_FLOATS * sizeof(float);   // ~209 KB
    cudaFuncSetAttribute(proj_mma_kernel,
                         cudaFuncAttributeMaxDynamicSharedMemorySize, smem_bytes);
    proj_mma_kernel<<<(N + 127) / 128, 512, smem_bytes>>>(x, logd, N);

    int warps_per_block = 256 / 32;
    int blocks = (N + warps_per_block - 1) / warps_per_block;
    edge_kernel<<<blocks, 256>>>(eidx, logt, out, N, deg, topk);

    const int repair_smem = REPAIR_SMEM_FLOATS * sizeof(float);
    cudaFuncSetAttribute(repair_kernel,
                         cudaFuncAttributeMaxDynamicSharedMemorySize, repair_smem);
    repair_kernel<<<148, 256, repair_smem>>>(eidx, logt, x, W, logd, out, N, deg, topk);
}